// round 2
// baseline (speedup 1.0000x reference)
#include <cuda_runtime.h>
#include <cstdint>

// Problem constants: B=2, S=1024, D=2048, F=8192, E=4, K=2
#define TT 2048   // tokens = B*S
#define TD 2048   // d_model
#define TF 8192   // d_ff
#define TE 4      // experts
#define NA 4096   // assignments = TT * K

// ---------------- device scratch (static; no runtime alloc) ----------------
__device__ int   g_counts[TE];
__device__ int   g_fill[TE];
__device__ int   g_offs[TE + 1];
__device__ int   g_eidx[NA];
__device__ float g_gate[NA];
__device__ int   g_rowmap[NA];    // segment row -> assignment id (t*2+k)
__device__ float g_rowgate[NA];   // segment row -> gate value
__device__ float g_H[(size_t)NA * TF];   // 134 MB hidden activations
__device__ float g_Y[(size_t)NA * TD];   // 33.5 MB per-assignment outputs

// ---------------- helpers ----------------
__device__ __forceinline__ uint32_t f2tf(float f) {
    uint32_t u;
    asm("cvt.rna.tf32.f32 %0, %1;" : "=r"(u) : "f"(f));
    return u;
}
__device__ __forceinline__ uint4 cvt4(float4 v) {
    uint4 r;
    r.x = f2tf(v.x); r.y = f2tf(v.y); r.z = f2tf(v.z); r.w = f2tf(v.w);
    return r;
}
__device__ __forceinline__ void mma_tf32(float* c,
                                         uint32_t a0, uint32_t a1, uint32_t a2, uint32_t a3,
                                         uint32_t b0, uint32_t b1) {
    asm volatile(
        "mma.sync.aligned.m16n8k8.row.col.f32.tf32.tf32.f32 "
        "{%0,%1,%2,%3}, {%4,%5,%6,%7}, {%8,%9}, {%0,%1,%2,%3};"
        : "+f"(c[0]), "+f"(c[1]), "+f"(c[2]), "+f"(c[3])
        : "r"(a0), "r"(a1), "r"(a2), "r"(a3), "r"(b0), "r"(b1));
}

// ---------------- routing ----------------
__global__ void zero_kernel() {
    int i = threadIdx.x;
    if (i < TE) { g_counts[i] = 0; g_fill[i] = 0; }
}

__global__ void router_kernel(const float* __restrict__ x, const float* __restrict__ Wr) {
    int gw   = (int)((blockIdx.x * blockDim.x + threadIdx.x) >> 5);  // one warp per token
    int lane = threadIdx.x & 31;
    if (gw >= TT) return;
    const float* xr = x + (size_t)gw * TD;
    float a0 = 0.f, a1 = 0.f, a2 = 0.f, a3 = 0.f;
    for (int d = lane; d < TD; d += 32) {
        float xv = xr[d];
        float4 w = *(const float4*)(Wr + d * 4);
        a0 += xv * w.x; a1 += xv * w.y; a2 += xv * w.z; a3 += xv * w.w;
    }
    #pragma unroll
    for (int o = 16; o; o >>= 1) {
        a0 += __shfl_xor_sync(0xffffffffu, a0, o);
        a1 += __shfl_xor_sync(0xffffffffu, a1, o);
        a2 += __shfl_xor_sync(0xffffffffu, a2, o);
        a3 += __shfl_xor_sync(0xffffffffu, a3, o);
    }
    if (lane == 0) {
        float l[4] = {a0, a1, a2, a3};
        float m = fmaxf(fmaxf(l[0], l[1]), fmaxf(l[2], l[3]));
        float p[4]; float s = 0.f;
        #pragma unroll
        for (int i = 0; i < 4; i++) { p[i] = __expf(l[i] - m); s += p[i]; }
        float inv = 1.0f / s;
        int i0 = 0;
        #pragma unroll
        for (int i = 1; i < 4; i++) if (p[i] > p[i0]) i0 = i;
        int i1 = (i0 == 0) ? 1 : 0;
        #pragma unroll
        for (int i = 0; i < 4; i++) if (i != i0 && p[i] > p[i1]) i1 = i;
        g_eidx[gw * 2]     = i0; g_gate[gw * 2]     = p[i0] * inv;
        g_eidx[gw * 2 + 1] = i1; g_gate[gw * 2 + 1] = p[i1] * inv;
        atomicAdd(&g_counts[i0], 1);
        atomicAdd(&g_counts[i1], 1);
    }
}

__global__ void offsets_kernel() {
    if (threadIdx.x == 0) {
        int s = 0;
        for (int e = 0; e < TE; e++) { g_offs[e] = s; s += g_counts[e]; }
        g_offs[TE] = s;
    }
}

__global__ void scatter_kernel() {
    int a = blockIdx.x * blockDim.x + threadIdx.x;
    if (a >= NA) return;
    int e = g_eidx[a];
    int pos = g_offs[e] + atomicAdd(&g_fill[e], 1);
    g_rowmap[pos]  = a;
    g_rowgate[pos] = g_gate[a];
}

// ---------------- GEMM1: H = silu(Xe*Wg) * (Xe*Wu) ----------------
// Tile 64(M) x 64(N), KB=32 over D. 8 warps (2x4), warp tile 32x16, tf32 mma.
__global__ __launch_bounds__(256, 2) void gemm1_kernel(
    const float* __restrict__ x, const float* __restrict__ Wg, const float* __restrict__ Wu) {
    __shared__ __align__(16) uint32_t As[64][36];
    __shared__ __align__(16) uint32_t Bgs[32][72];
    __shared__ __align__(16) uint32_t Bus[32][72];

    const int e    = blockIdx.z;
    const int cnt  = g_counts[e];
    const int row0 = blockIdx.x * 64;
    if (row0 >= cnt) return;
    const int segbase = g_offs[e];
    const int f0   = blockIdx.y * 64;

    const int tid  = threadIdx.x;
    const int lane = tid & 31;
    const int warp = tid >> 5;
    const int grp  = lane >> 2;   // 0..7
    const int t4   = lane & 3;    // 0..3
    const int wm   = warp & 1;    // 2 warp rows (32 each)
    const int wn   = warp >> 1;   // 4 warp cols (16 each)

    // A (gathered token rows): thread loads rows rA and rA+32, float4 at col c8
    const int rA = tid >> 3;
    const int c8 = (tid & 7) << 2;
    const float* ap0 = nullptr;
    const float* ap1 = nullptr;
    if (row0 + rA < cnt)
        ap0 = x + (size_t)(g_rowmap[segbase + row0 + rA] >> 1) * TD + c8;
    if (row0 + rA + 32 < cnt)
        ap1 = x + (size_t)(g_rowmap[segbase + row0 + rA + 32] >> 1) * TD + c8;

    // B: rows kB and kB+16, float4 at col c16
    const int kB  = tid >> 4;
    const int c16 = (tid & 15) << 2;
    const float* bgp = Wg + (size_t)e * TD * TF + (size_t)kB * TF + f0 + c16;
    const float* bup = Wu + (size_t)e * TD * TF + (size_t)kB * TF + f0 + c16;

    float accG[2][2][4], accU[2][2][4];
    #pragma unroll
    for (int i = 0; i < 2; i++)
        #pragma unroll
        for (int j = 0; j < 2; j++)
            #pragma unroll
            for (int q = 0; q < 4; q++) { accG[i][j][q] = 0.f; accU[i][j][q] = 0.f; }

    for (int kb = 0; kb < TD; kb += 32) {
        float4 av0 = ap0 ? *(const float4*)(ap0 + kb) : make_float4(0.f, 0.f, 0.f, 0.f);
        float4 av1 = ap1 ? *(const float4*)(ap1 + kb) : make_float4(0.f, 0.f, 0.f, 0.f);
        float4 gv0 = *(const float4*)(bgp + (size_t)kb * TF);
        float4 gv1 = *(const float4*)(bgp + (size_t)(kb + 16) * TF);
        float4 uv0 = *(const float4*)(bup + (size_t)kb * TF);
        float4 uv1 = *(const float4*)(bup + (size_t)(kb + 16) * TF);
        __syncthreads();
        *(uint4*)&As[rA][c8]        = cvt4(av0);
        *(uint4*)&As[rA + 32][c8]   = cvt4(av1);
        *(uint4*)&Bgs[kB][c16]      = cvt4(gv0);
        *(uint4*)&Bgs[kB + 16][c16] = cvt4(gv1);
        *(uint4*)&Bus[kB][c16]      = cvt4(uv0);
        *(uint4*)&Bus[kB + 16][c16] = cvt4(uv1);
        __syncthreads();

        #pragma unroll
        for (int ks = 0; ks < 4; ks++) {
            const int kk = ks * 8 + t4;
            uint32_t af[2][4];
            #pragma unroll
            for (int mi = 0; mi < 2; mi++) {
                const int r = wm * 32 + mi * 16 + grp;
                af[mi][0] = As[r][kk];
                af[mi][1] = As[r + 8][kk];
                af[mi][2] = As[r][kk + 4];
                af[mi][3] = As[r + 8][kk + 4];
            }
            #pragma unroll
            for (int ni = 0; ni < 2; ni++) {
                const int c = wn * 16 + ni * 8 + grp;
                uint32_t bg0 = Bgs[kk][c], bg1 = Bgs[kk + 4][c];
                uint32_t bu0 = Bus[kk][c], bu1 = Bus[kk + 4][c];
                #pragma unroll
                for (int mi = 0; mi < 2; mi++) {
                    mma_tf32(accG[mi][ni], af[mi][0], af[mi][1], af[mi][2], af[mi][3], bg0, bg1);
                    mma_tf32(accU[mi][ni], af[mi][0], af[mi][1], af[mi][2], af[mi][3], bu0, bu1);
                }
            }
        }
    }

    // epilogue: h = g * u * sigmoid(g) -> g_H
    #pragma unroll
    for (int mi = 0; mi < 2; mi++) {
        #pragma unroll
        for (int ni = 0; ni < 2; ni++) {
            const int rl = wm * 32 + mi * 16 + grp;
            const int c  = f0 + wn * 16 + ni * 8 + t4 * 2;
            int gr = row0 + rl;
            if (gr < cnt) {
                float g0 = accG[mi][ni][0], u0 = accU[mi][ni][0];
                float g1 = accG[mi][ni][1], u1 = accU[mi][ni][1];
                float2 h;
                h.x = __fdividef(g0 * u0, 1.0f + __expf(-g0));
                h.y = __fdividef(g1 * u1, 1.0f + __expf(-g1));
                *(float2*)&g_H[(size_t)(segbase + gr) * TF + c] = h;
            }
            gr = row0 + rl + 8;
            if (gr < cnt) {
                float g0 = accG[mi][ni][2], u0 = accU[mi][ni][2];
                float g1 = accG[mi][ni][3], u1 = accU[mi][ni][3];
                float2 h;
                h.x = __fdividef(g0 * u0, 1.0f + __expf(-g0));
                h.y = __fdividef(g1 * u1, 1.0f + __expf(-g1));
                *(float2*)&g_H[(size_t)(segbase + gr) * TF + c] = h;
            }
        }
    }
}

// ---------------- GEMM2: Y = gate * (H * Wd), scattered to (t,k) slots ----------------
__global__ __launch_bounds__(256, 2) void gemm2_kernel(const float* __restrict__ Wd) {
    __shared__ __align__(16) uint32_t As[64][36];
    __shared__ __align__(16) uint32_t Bs[32][72];

    const int e    = blockIdx.z;
    const int cnt  = g_counts[e];
    const int row0 = blockIdx.x * 64;
    if (row0 >= cnt) return;
    const int segbase = g_offs[e];
    const int n0   = blockIdx.y * 64;

    const int tid  = threadIdx.x;
    const int lane = tid & 31;
    const int warp = tid >> 5;
    const int grp  = lane >> 2;
    const int t4   = lane & 3;
    const int wm   = warp & 1;
    const int wn   = warp >> 1;

    const int rA = tid >> 3;
    const int c8 = (tid & 7) << 2;
    const float* ap0 = nullptr;
    const float* ap1 = nullptr;
    if (row0 + rA < cnt)
        ap0 = g_H + (size_t)(segbase + row0 + rA) * TF + c8;
    if (row0 + rA + 32 < cnt)
        ap1 = g_H + (size_t)(segbase + row0 + rA + 32) * TF + c8;

    const int kB  = tid >> 4;
    const int c16 = (tid & 15) << 2;
    const float* bdp = Wd + (size_t)e * TF * TD + (size_t)kB * TD + n0 + c16;

    float acc[2][2][4];
    #pragma unroll
    for (int i = 0; i < 2; i++)
        #pragma unroll
        for (int j = 0; j < 2; j++)
            #pragma unroll
            for (int q = 0; q < 4; q++) acc[i][j][q] = 0.f;

    for (int kb = 0; kb < TF; kb += 32) {
        float4 av0 = ap0 ? *(const float4*)(ap0 + kb) : make_float4(0.f, 0.f, 0.f, 0.f);
        float4 av1 = ap1 ? *(const float4*)(ap1 + kb) : make_float4(0.f, 0.f, 0.f, 0.f);
        float4 bv0 = *(const float4*)(bdp + (size_t)kb * TD);
        float4 bv1 = *(const float4*)(bdp + (size_t)(kb + 16) * TD);
        __syncthreads();
        *(uint4*)&As[rA][c8]       = cvt4(av0);
        *(uint4*)&As[rA + 32][c8]  = cvt4(av1);
        *(uint4*)&Bs[kB][c16]      = cvt4(bv0);
        *(uint4*)&Bs[kB + 16][c16] = cvt4(bv1);
        __syncthreads();

        #pragma unroll
        for (int ks = 0; ks < 4; ks++) {
            const int kk = ks * 8 + t4;
            uint32_t af[2][4];
            #pragma unroll
            for (int mi = 0; mi < 2; mi++) {
                const int r = wm * 32 + mi * 16 + grp;
                af[mi][0] = As[r][kk];
                af[mi][1] = As[r + 8][kk];
                af[mi][2] = As[r][kk + 4];
                af[mi][3] = As[r + 8][kk + 4];
            }
            #pragma unroll
            for (int ni = 0; ni < 2; ni++) {
                const int c = wn * 16 + ni * 8 + grp;
                uint32_t b0 = Bs[kk][c], b1 = Bs[kk + 4][c];
                #pragma unroll
                for (int mi = 0; mi < 2; mi++)
                    mma_tf32(acc[mi][ni], af[mi][0], af[mi][1], af[mi][2], af[mi][3], b0, b1);
            }
        }
    }

    #pragma unroll
    for (int mi = 0; mi < 2; mi++) {
        #pragma unroll
        for (int ni = 0; ni < 2; ni++) {
            const int rl = wm * 32 + mi * 16 + grp;
            const int c  = n0 + wn * 16 + ni * 8 + t4 * 2;
            int gr = row0 + rl;
            if (gr < cnt) {
                int   a = g_rowmap[segbase + gr];
                float w = g_rowgate[segbase + gr];
                float2 v; v.x = w * acc[mi][ni][0]; v.y = w * acc[mi][ni][1];
                *(float2*)&g_Y[(size_t)a * TD + c] = v;
            }
            gr = row0 + rl + 8;
            if (gr < cnt) {
                int   a = g_rowmap[segbase + gr];
                float w = g_rowgate[segbase + gr];
                float2 v; v.x = w * acc[mi][ni][2]; v.y = w * acc[mi][ni][3];
                *(float2*)&g_Y[(size_t)a * TD + c] = v;
            }
        }
    }
}

// ---------------- combine: out[t] = Y[t,0] + Y[t,1] ----------------
__global__ void combine_kernel(float* __restrict__ out) {
    int i = blockIdx.x * blockDim.x + threadIdx.x;   // TT*TD = 4194304
    if (i >= TT * TD) return;
    int t = i >> 11;      // / TD
    int d = i & (TD - 1);
    out[i] = g_Y[(size_t)(2 * t) * TD + d] + g_Y[(size_t)(2 * t + 1) * TD + d];
}

// ---------------- launch ----------------
extern "C" void kernel_launch(void* const* d_in, const int* in_sizes, int n_in,
                              void* d_out, int out_size) {
    const float* x  = (const float*)d_in[0];
    const float* Wr = (const float*)d_in[1];
    const float* Wg = (const float*)d_in[2];
    const float* Wu = (const float*)d_in[3];
    const float* Wd = (const float*)d_in[4];
    float* out = (float*)d_out;

    zero_kernel<<<1, 32>>>();
    router_kernel<<<TT / 8, 256>>>(x, Wr);     // one warp per token
    offsets_kernel<<<1, 1>>>();
    scatter_kernel<<<NA / 256, 256>>>();

    dim3 grid1(32, TF / 64, TE);               // row-tile fastest: B-panel reuse via L2
    gemm1_kernel<<<grid1, 256>>>(x, Wg, Wu);

    dim3 grid2(32, TD / 64, TE);
    gemm2_kernel<<<grid2, 256>>>(Wd);

    combine_kernel<<<(TT * TD) / 256, 256>>>(out);
}

// round 4
// speedup vs baseline: 1.1510x; 1.1510x over previous
#include <cuda_runtime.h>
#include <cstdint>

// Problem constants: B=2, S=1024, D=2048, F=8192, E=4, K=2
#define TT 2048
#define TD 2048
#define TF 8192
#define TE 4
#define NA 4096

#define KC 16           // K per stage
#define NSTG 4

// GEMM1 smem (floats): A[128][20] + G[16][72] + U[16][72] per stage
#define G1_SSTGF (128*20 + 16*72 + 16*72)      // 4864 floats = 19456 B
#define G1_ABASE 0
#define G1_GBASE (128*20)                      // 2560
#define G1_UBASE (128*20 + 16*72)              // 3712
#define G1_SMEM  (G1_SSTGF*NSTG*4 + 512)       // + rid[128]

// GEMM2 smem (floats): A[128][20] + B[16][136] per stage
#define G2_SSTGF (128*20 + 16*136)             // 4736 floats = 18944 B
#define G2_ABASE 0
#define G2_BBASE (128*20)
#define G2_SMEM  (G2_SSTGF*NSTG*4)

// ---------------- device scratch ----------------
__device__ int   g_counts[TE];
__device__ int   g_fill[TE];
__device__ int   g_offs[TE + 1];
__device__ int   g_eidx[NA];
__device__ float g_gate[NA];
__device__ int   g_rowmap[NA];
__device__ float g_rowgate[NA];
__device__ float g_H[(size_t)NA * TF];
__device__ float g_Y[(size_t)NA * TD];

// ---------------- helpers ----------------
__device__ __forceinline__ uint32_t f2tf(float f) {
    uint32_t u;
    asm("cvt.rna.tf32.f32 %0, %1;" : "=r"(u) : "f"(f));
    return u;
}
__device__ __forceinline__ uint32_t smem_u32(const void* p) {
    uint32_t a;
    asm("{ .reg .u64 t; cvta.to.shared.u64 t, %1; cvt.u32.u64 %0, t; }" : "=r"(a) : "l"(p));
    return a;
}
__device__ __forceinline__ void cpa16(uint32_t dst, const float* src, uint32_t valid) {
    asm volatile("cp.async.cg.shared.global [%0], [%1], 16, %2;" :: "r"(dst), "l"(src), "r"(valid) : "memory");
}
__device__ __forceinline__ void cpa_commit() { asm volatile("cp.async.commit_group;" ::: "memory"); }
__device__ __forceinline__ void cpa_wait2()  { asm volatile("cp.async.wait_group 2;" ::: "memory"); }

__device__ __forceinline__ void mma_tf32(float* c, const uint32_t* a, uint32_t b0, uint32_t b1) {
    asm volatile(
        "mma.sync.aligned.m16n8k8.row.col.f32.tf32.tf32.f32 "
        "{%0,%1,%2,%3}, {%4,%5,%6,%7}, {%8,%9}, {%0,%1,%2,%3};"
        : "+f"(c[0]), "+f"(c[1]), "+f"(c[2]), "+f"(c[3])
        : "r"(a[0]), "r"(a[1]), "r"(a[2]), "r"(a[3]), "r"(b0), "r"(b1));
}

// ---------------- routing ----------------
__global__ void zero_kernel() {
    int i = threadIdx.x;
    if (i < TE) { g_counts[i] = 0; g_fill[i] = 0; }
}

__global__ void router_kernel(const float* __restrict__ x, const float* __restrict__ Wr) {
    int gw   = (int)((blockIdx.x * blockDim.x + threadIdx.x) >> 5);
    int lane = threadIdx.x & 31;
    if (gw >= TT) return;
    const float* xr = x + (size_t)gw * TD;
    float a0 = 0.f, a1 = 0.f, a2 = 0.f, a3 = 0.f;
    for (int d = lane; d < TD; d += 32) {
        float xv = xr[d];
        float4 w = *(const float4*)(Wr + d * 4);
        a0 += xv * w.x; a1 += xv * w.y; a2 += xv * w.z; a3 += xv * w.w;
    }
    #pragma unroll
    for (int o = 16; o; o >>= 1) {
        a0 += __shfl_xor_sync(0xffffffffu, a0, o);
        a1 += __shfl_xor_sync(0xffffffffu, a1, o);
        a2 += __shfl_xor_sync(0xffffffffu, a2, o);
        a3 += __shfl_xor_sync(0xffffffffu, a3, o);
    }
    if (lane == 0) {
        float l[4] = {a0, a1, a2, a3};
        float m = fmaxf(fmaxf(l[0], l[1]), fmaxf(l[2], l[3]));
        float p[4]; float s = 0.f;
        #pragma unroll
        for (int i = 0; i < 4; i++) { p[i] = __expf(l[i] - m); s += p[i]; }
        float inv = 1.0f / s;
        int i0 = 0;
        #pragma unroll
        for (int i = 1; i < 4; i++) if (p[i] > p[i0]) i0 = i;
        int i1 = (i0 == 0) ? 1 : 0;
        #pragma unroll
        for (int i = 0; i < 4; i++) if (i != i0 && p[i] > p[i1]) i1 = i;
        g_eidx[gw * 2]     = i0; g_gate[gw * 2]     = p[i0] * inv;
        g_eidx[gw * 2 + 1] = i1; g_gate[gw * 2 + 1] = p[i1] * inv;
        atomicAdd(&g_counts[i0], 1);
        atomicAdd(&g_counts[i1], 1);
    }
}

__global__ void offsets_kernel() {
    if (threadIdx.x == 0) {
        int s = 0;
        for (int e = 0; e < TE; e++) { g_offs[e] = s; s += g_counts[e]; }
        g_offs[TE] = s;
    }
}

__global__ void scatter_kernel() {
    int a = blockIdx.x * blockDim.x + threadIdx.x;
    if (a >= NA) return;
    int e = g_eidx[a];
    int pos = g_offs[e] + atomicAdd(&g_fill[e], 1);
    g_rowmap[pos]  = a;
    g_rowgate[pos] = g_gate[a];
}

// ---------------- GEMM1: H = silu(Xe*Wg) * (Xe*Wu) ----------------
// CTA tile: M=128 gathered rows x N=64 f-cols, both G and U. 8 warps (4m x 2n),
// warp tile 32x32 per matrix. tf32 m16n8k8, 4-stage cp.async.
__global__ __launch_bounds__(256, 2) void gemm1_kernel(
    const float* __restrict__ x, const float* __restrict__ Wg, const float* __restrict__ Wu) {
    const int e    = blockIdx.z;
    const int cnt  = g_counts[e];
    const int row0 = blockIdx.x * 128;
    if (row0 >= cnt) return;
    const int seg = g_offs[e];
    const int f0  = blockIdx.y * 64;

    extern __shared__ float sm[];
    float* stg = sm;                                   // 4 stages
    int*   rid = (int*)(sm + G1_SSTGF * NSTG);

    const int tid = threadIdx.x, lane = tid & 31, warp = tid >> 5;
    const int grp = lane >> 2, t4 = lane & 3;

    if (tid < 128) {
        int r = row0 + tid;
        rid[tid] = (r < cnt) ? (g_rowmap[seg + r] >> 1) : -1;
    }
    __syncthreads();

    // loader mapping
    const int arow = tid >> 1, ac = (tid & 1) * 2;     // A: 2 x 16B chunks
    const int tok  = rid[arow];
    const uint32_t aval = (tok >= 0) ? 16u : 0u;
    const float* aptr = x + (size_t)(tok < 0 ? 0 : tok) * TD + ac * 4;
    const int brow = tid >> 4, bc = tid & 15;          // G/U: 1 x 16B chunk each
    const float* gptr = Wg + ((size_t)e * TD + brow) * TF + f0 + bc * 4;
    const float* uptr = Wu + ((size_t)e * TD + brow) * TF + f0 + bc * 4;

    const uint32_t smb = smem_u32(sm);
    const uint32_t aoffb = smb + (arow * 20 + ac * 4) * 4;
    const uint32_t goffb = smb + (G1_GBASE + brow * 72 + bc * 4) * 4;
    const uint32_t uoffb = smb + (G1_UBASE + brow * 72 + bc * 4) * 4;
    const uint32_t SSB = G1_SSTGF * 4;

    #pragma unroll
    for (int s = 0; s < NSTG - 1; s++) {
        int kb = s * KC;
        cpa16(aoffb + s * SSB,      aptr + kb,     aval);
        cpa16(aoffb + s * SSB + 16, aptr + kb + 4, aval);
        cpa16(goffb + s * SSB, gptr + (size_t)kb * TF, 16u);
        cpa16(uoffb + s * SSB, uptr + (size_t)kb * TF, 16u);
        cpa_commit();
    }

    float accG[2][4][4], accU[2][4][4];
    #pragma unroll
    for (int i = 0; i < 2; i++)
        #pragma unroll
        for (int j = 0; j < 4; j++)
            #pragma unroll
            for (int q = 0; q < 4; q++) { accG[i][j][q] = 0.f; accU[i][j][q] = 0.f; }

    const int mrow0 = (warp & 3) * 32 + grp;
    const int ncol0 = (warp >> 2) * 32 + grp;
    const int NC = TD / KC;   // 128

    #pragma unroll 1
    for (int i = 0; i < NC; i++) {
        cpa_wait2();
        __syncthreads();
        {   // issue stage i+3 (or empty)
            int s = (i + NSTG - 1) & 3;
            int kb = (i + NSTG - 1) * KC;
            if (kb < TD) {
                cpa16(aoffb + s * SSB,      aptr + kb,     aval);
                cpa16(aoffb + s * SSB + 16, aptr + kb + 4, aval);
                cpa16(goffb + s * SSB, gptr + (size_t)kb * TF, 16u);
                cpa16(uoffb + s * SSB, uptr + (size_t)kb * TF, 16u);
            }
            cpa_commit();
        }
        const float* sb = stg + (i & 3) * G1_SSTGF;
        #pragma unroll
        for (int ks = 0; ks < 2; ks++) {
            const int kk = ks * 8 + t4;
            uint32_t a[2][4];
            #pragma unroll
            for (int mi = 0; mi < 2; mi++) {
                const float* ab = sb + (mrow0 + mi * 16) * 20 + kk;
                a[mi][0] = f2tf(ab[0]);
                a[mi][1] = f2tf(ab[8 * 20]);
                a[mi][2] = f2tf(ab[4]);
                a[mi][3] = f2tf(ab[8 * 20 + 4]);
            }
            #pragma unroll
            for (int ni = 0; ni < 4; ni++) {
                const int cb = ncol0 + ni * 8;
                const float* gb = sb + G1_GBASE + kk * 72 + cb;
                const float* ub = sb + G1_UBASE + kk * 72 + cb;
                uint32_t b0 = f2tf(gb[0]), b1 = f2tf(gb[4 * 72]);
                uint32_t c0 = f2tf(ub[0]), c1 = f2tf(ub[4 * 72]);
                #pragma unroll
                for (int mi = 0; mi < 2; mi++) {
                    mma_tf32(accG[mi][ni], a[mi], b0, b1);
                    mma_tf32(accU[mi][ni], a[mi], c0, c1);
                }
            }
        }
    }

    // epilogue: h = silu(g)*u -> g_H
    #pragma unroll
    for (int mi = 0; mi < 2; mi++) {
        const int rl = (warp & 3) * 32 + mi * 16 + grp;
        const int r0 = row0 + rl, r1 = row0 + rl + 8;
        #pragma unroll
        for (int ni = 0; ni < 4; ni++) {
            const int col = f0 + (warp >> 2) * 32 + ni * 8 + t4 * 2;
            if (r0 < cnt) {
                float gg0 = accG[mi][ni][0], uu0 = accU[mi][ni][0];
                float gg1 = accG[mi][ni][1], uu1 = accU[mi][ni][1];
                float2 h;
                h.x = __fdividef(gg0 * uu0, 1.0f + __expf(-gg0));
                h.y = __fdividef(gg1 * uu1, 1.0f + __expf(-gg1));
                *(float2*)&g_H[(size_t)(seg + r0) * TF + col] = h;
            }
            if (r1 < cnt) {
                float gg0 = accG[mi][ni][2], uu0 = accU[mi][ni][2];
                float gg1 = accG[mi][ni][3], uu1 = accU[mi][ni][3];
                float2 h;
                h.x = __fdividef(gg0 * uu0, 1.0f + __expf(-gg0));
                h.y = __fdividef(gg1 * uu1, 1.0f + __expf(-gg1));
                *(float2*)&g_H[(size_t)(seg + r1) * TF + col] = h;
            }
        }
    }
}

// ---------------- GEMM2: Y = gate * (H * Wd) ----------------
// CTA tile: M=128 x N=128 d-cols. 8 warps (4m x 2n), warp tile 32x64.
__global__ __launch_bounds__(256, 2) void gemm2_kernel(const float* __restrict__ Wd) {
    const int e    = blockIdx.z;
    const int cnt  = g_counts[e];
    const int row0 = blockIdx.x * 128;
    if (row0 >= cnt) return;
    const int seg = g_offs[e];
    const int n0  = blockIdx.y * 128;

    extern __shared__ float sm[];
    float* stg = sm;

    const int tid = threadIdx.x, lane = tid & 31, warp = tid >> 5;
    const int grp = lane >> 2, t4 = lane & 3;

    const int arow = tid >> 1, ac = (tid & 1) * 2;
    const uint32_t aval = (row0 + arow < cnt) ? 16u : 0u;
    const float* aptr = g_H + (size_t)(seg + ((row0 + arow < cnt) ? row0 + arow : 0)) * TF + ac * 4;
    const int brow = tid >> 4, bc2 = (tid & 15) * 2;   // B: 2 x 16B chunks
    const float* bptr = Wd + ((size_t)e * TF + brow) * TD + n0 + bc2 * 4;

    const uint32_t smb = smem_u32(sm);
    const uint32_t aoffb = smb + (arow * 20 + ac * 4) * 4;
    const uint32_t boffb = smb + (G2_BBASE + brow * 136 + bc2 * 4) * 4;
    const uint32_t SSB = G2_SSTGF * 4;

    #pragma unroll
    for (int s = 0; s < NSTG - 1; s++) {
        int kb = s * KC;
        cpa16(aoffb + s * SSB,      aptr + kb,     aval);
        cpa16(aoffb + s * SSB + 16, aptr + kb + 4, aval);
        cpa16(boffb + s * SSB,      bptr + (size_t)kb * TD,     16u);
        cpa16(boffb + s * SSB + 16, bptr + (size_t)kb * TD + 4, 16u);
        cpa_commit();
    }

    float acc[2][8][4];
    #pragma unroll
    for (int i = 0; i < 2; i++)
        #pragma unroll
        for (int j = 0; j < 8; j++)
            #pragma unroll
            for (int q = 0; q < 4; q++) acc[i][j][q] = 0.f;

    const int mrow0 = (warp & 3) * 32 + grp;
    const int ncol0 = (warp >> 2) * 64 + grp;
    const int NC = TF / KC;   // 512

    #pragma unroll 1
    for (int i = 0; i < NC; i++) {
        cpa_wait2();
        __syncthreads();
        {
            int s = (i + NSTG - 1) & 3;
            int kb = (i + NSTG - 1) * KC;
            if (kb < TF) {
                cpa16(aoffb + s * SSB,      aptr + kb,     aval);
                cpa16(aoffb + s * SSB + 16, aptr + kb + 4, aval);
                cpa16(boffb + s * SSB,      bptr + (size_t)kb * TD,     16u);
                cpa16(boffb + s * SSB + 16, bptr + (size_t)kb * TD + 4, 16u);
            }
            cpa_commit();
        }
        const float* sb = stg + (i & 3) * G2_SSTGF;
        #pragma unroll
        for (int ks = 0; ks < 2; ks++) {
            const int kk = ks * 8 + t4;
            uint32_t a[2][4];
            #pragma unroll
            for (int mi = 0; mi < 2; mi++) {
                const float* ab = sb + (mrow0 + mi * 16) * 20 + kk;
                a[mi][0] = f2tf(ab[0]);
                a[mi][1] = f2tf(ab[8 * 20]);
                a[mi][2] = f2tf(ab[4]);
                a[mi][3] = f2tf(ab[8 * 20 + 4]);
            }
            #pragma unroll
            for (int ni = 0; ni < 8; ni++) {
                const float* bb = sb + G2_BBASE + kk * 136 + ncol0 + ni * 8;
                uint32_t b0 = f2tf(bb[0]), b1 = f2tf(bb[4 * 136]);
                #pragma unroll
                for (int mi = 0; mi < 2; mi++)
                    mma_tf32(acc[mi][ni], a[mi], b0, b1);
            }
        }
    }

    // epilogue: scale by gate, scatter to assignment slot
    #pragma unroll
    for (int mi = 0; mi < 2; mi++) {
        const int rl = (warp & 3) * 32 + mi * 16 + grp;
        const int r0 = row0 + rl, r1 = row0 + rl + 8;
        int a0i = 0, a1i = 0; float w0 = 0.f, w1 = 0.f;
        if (r0 < cnt) { a0i = g_rowmap[seg + r0]; w0 = g_rowgate[seg + r0]; }
        if (r1 < cnt) { a1i = g_rowmap[seg + r1]; w1 = g_rowgate[seg + r1]; }
        #pragma unroll
        for (int ni = 0; ni < 8; ni++) {
            const int col = n0 + (warp >> 2) * 64 + ni * 8 + t4 * 2;
            if (r0 < cnt) {
                float2 v; v.x = w0 * acc[mi][ni][0]; v.y = w0 * acc[mi][ni][1];
                *(float2*)&g_Y[(size_t)a0i * TD + col] = v;
            }
            if (r1 < cnt) {
                float2 v; v.x = w1 * acc[mi][ni][2]; v.y = w1 * acc[mi][ni][3];
                *(float2*)&g_Y[(size_t)a1i * TD + col] = v;
            }
        }
    }
}

// ---------------- combine: out[t] = Y[t,0] + Y[t,1] ----------------
__global__ void combine_kernel(float* __restrict__ out) {
    int i = blockIdx.x * blockDim.x + threadIdx.x;
    if (i >= TT * TD) return;
    int t = i >> 11;
    int d = i & (TD - 1);
    out[i] = g_Y[(size_t)(2 * t) * TD + d] + g_Y[(size_t)(2 * t + 1) * TD + d];
}

// ---------------- launch ----------------
extern "C" void kernel_launch(void* const* d_in, const int* in_sizes, int n_in,
                              void* d_out, int out_size) {
    const float* x  = (const float*)d_in[0];
    const float* Wr = (const float*)d_in[1];
    const float* Wg = (const float*)d_in[2];
    const float* Wu = (const float*)d_in[3];
    const float* Wd = (const float*)d_in[4];
    float* out = (float*)d_out;

    static int attr_done = 0;
    if (!attr_done) {
        cudaFuncSetAttribute(gemm1_kernel, cudaFuncAttributeMaxDynamicSharedMemorySize, G1_SMEM);
        cudaFuncSetAttribute(gemm2_kernel, cudaFuncAttributeMaxDynamicSharedMemorySize, G2_SMEM);
        attr_done = 1;
    }

    zero_kernel<<<1, 32>>>();
    router_kernel<<<TT / 8, 256>>>(x, Wr);
    offsets_kernel<<<1, 1>>>();
    scatter_kernel<<<NA / 256, 256>>>();

    gemm1_kernel<<<dim3(32, TF / 64, TE), 256, G1_SMEM>>>(x, Wg, Wu);
    gemm2_kernel<<<dim3(32, TD / 128, TE), 256, G2_SMEM>>>(Wd);

    combine_kernel<<<(TT * TD) / 256, 256>>>(out);
}

// round 5
// speedup vs baseline: 2.3583x; 2.0490x over previous
#include <cuda_runtime.h>
#include <cuda_fp16.h>
#include <cstdint>

// Problem constants: B=2, S=1024, D=2048, F=8192, E=4, K=2
#define TT 2048
#define TD 2048
#define TF 8192
#define TE 4
#define NA 4096

#define KC 32           // K per stage (fp16)
#define NSTG 4

// GEMM1 smem (halfs/stage): A[128][40] + G[32][72] + U[32][72]
#define G1_STGH (128*40 + 32*72 + 32*72)    // 9728 halfs = 19456 B
#define G1_AB 0
#define G1_GB (128*40)                      // 5120
#define G1_UB (128*40 + 32*72)              // 7424
#define G1_SMEM (G1_STGH*NSTG*2 + 512)

// GEMM2 smem (halfs/stage): A[128][40] + B0[32][72] + B1[32][72]
#define G2_STGH G1_STGH
#define G2_AB 0
#define G2_B0 (128*40)
#define G2_B1 (128*40 + 32*72)
#define G2_SMEM (G2_STGH*NSTG*2)

// ---------------- device scratch ----------------
__device__ int    g_counts[TE];
__device__ int    g_fill[TE];
__device__ int    g_offs[TE + 1];
__device__ int    g_eidx[NA];
__device__ float  g_gate[NA];
__device__ int    g_rowmap[NA];
__device__ float  g_rowgate[NA];
__device__ __half g_Xh[(size_t)TT * TD];
__device__ __half g_Wgh[(size_t)TE * TD * TF];
__device__ __half g_Wuh[(size_t)TE * TD * TF];
__device__ __half g_Wdh[(size_t)TE * TF * TD];
__device__ __half g_Hh[(size_t)NA * TF];
__device__ float  g_Y[(size_t)NA * TD];

// ---------------- helpers ----------------
__device__ __forceinline__ uint32_t smem_u32(const void* p) {
    uint32_t a;
    asm("{ .reg .u64 t; cvta.to.shared.u64 t, %1; cvt.u32.u64 %0, t; }" : "=r"(a) : "l"(p));
    return a;
}
__device__ __forceinline__ void cpa16(uint32_t dst, const void* src, uint32_t valid) {
    asm volatile("cp.async.cg.shared.global [%0], [%1], 16, %2;" :: "r"(dst), "l"(src), "r"(valid) : "memory");
}
__device__ __forceinline__ void cpa_commit() { asm volatile("cp.async.commit_group;" ::: "memory"); }
__device__ __forceinline__ void cpa_wait2()  { asm volatile("cp.async.wait_group 2;" ::: "memory"); }

__device__ __forceinline__ void ldmx4(uint32_t* r, uint32_t addr) {
    asm volatile("ldmatrix.sync.aligned.m8n8.x4.shared.b16 {%0,%1,%2,%3}, [%4];"
                 : "=r"(r[0]), "=r"(r[1]), "=r"(r[2]), "=r"(r[3]) : "r"(addr));
}
__device__ __forceinline__ void ldmx4t(uint32_t* r, uint32_t addr) {
    asm volatile("ldmatrix.sync.aligned.m8n8.x4.trans.shared.b16 {%0,%1,%2,%3}, [%4];"
                 : "=r"(r[0]), "=r"(r[1]), "=r"(r[2]), "=r"(r[3]) : "r"(addr));
}
__device__ __forceinline__ void mma_f16(float* c, const uint32_t* a, uint32_t b0, uint32_t b1) {
    asm volatile(
        "mma.sync.aligned.m16n8k16.row.col.f32.f16.f16.f32 "
        "{%0,%1,%2,%3}, {%4,%5,%6,%7}, {%8,%9}, {%0,%1,%2,%3};"
        : "+f"(c[0]), "+f"(c[1]), "+f"(c[2]), "+f"(c[3])
        : "r"(a[0]), "r"(a[1]), "r"(a[2]), "r"(a[3]), "r"(b0), "r"(b1));
}

// ---------------- routing ----------------
__global__ void zero_kernel() {
    int i = threadIdx.x;
    if (i < TE) { g_counts[i] = 0; g_fill[i] = 0; }
}

__global__ void router_kernel(const float* __restrict__ x, const float* __restrict__ Wr) {
    int gw   = (int)((blockIdx.x * blockDim.x + threadIdx.x) >> 5);
    int lane = threadIdx.x & 31;
    if (gw >= TT) return;
    const float* xr = x + (size_t)gw * TD;
    float a0 = 0.f, a1 = 0.f, a2 = 0.f, a3 = 0.f;
    for (int d = lane; d < TD; d += 32) {
        float xv = xr[d];
        float4 w = *(const float4*)(Wr + d * 4);
        a0 += xv * w.x; a1 += xv * w.y; a2 += xv * w.z; a3 += xv * w.w;
    }
    #pragma unroll
    for (int o = 16; o; o >>= 1) {
        a0 += __shfl_xor_sync(0xffffffffu, a0, o);
        a1 += __shfl_xor_sync(0xffffffffu, a1, o);
        a2 += __shfl_xor_sync(0xffffffffu, a2, o);
        a3 += __shfl_xor_sync(0xffffffffu, a3, o);
    }
    if (lane == 0) {
        float l[4] = {a0, a1, a2, a3};
        float m = fmaxf(fmaxf(l[0], l[1]), fmaxf(l[2], l[3]));
        float p[4]; float s = 0.f;
        #pragma unroll
        for (int i = 0; i < 4; i++) { p[i] = __expf(l[i] - m); s += p[i]; }
        float inv = 1.0f / s;
        int i0 = 0;
        #pragma unroll
        for (int i = 1; i < 4; i++) if (p[i] > p[i0]) i0 = i;
        int i1 = (i0 == 0) ? 1 : 0;
        #pragma unroll
        for (int i = 0; i < 4; i++) if (i != i0 && p[i] > p[i1]) i1 = i;
        g_eidx[gw * 2]     = i0; g_gate[gw * 2]     = p[i0] * inv;
        g_eidx[gw * 2 + 1] = i1; g_gate[gw * 2 + 1] = p[i1] * inv;
        atomicAdd(&g_counts[i0], 1);
        atomicAdd(&g_counts[i1], 1);
    }
}

__global__ void offsets_kernel() {
    if (threadIdx.x == 0) {
        int s = 0;
        for (int e = 0; e < TE; e++) { g_offs[e] = s; s += g_counts[e]; }
        g_offs[TE] = s;
    }
}

__global__ void scatter_kernel() {
    int a = blockIdx.x * blockDim.x + threadIdx.x;
    if (a >= NA) return;
    int e = g_eidx[a];
    int pos = g_offs[e] + atomicAdd(&g_fill[e], 1);
    g_rowmap[pos]  = a;
    g_rowgate[pos] = g_gate[a];
}

// ---------------- prep: fp32 -> fp16 conversion ----------------
__global__ void cvt_kernel(const float4* __restrict__ src, uint2* __restrict__ dst, int n4) {
    int i = blockIdx.x * blockDim.x + threadIdx.x;
    if (i >= n4) return;
    float4 v = src[i];
    __half2 lo = __floats2half2_rn(v.x, v.y);
    __half2 hi = __floats2half2_rn(v.z, v.w);
    uint2 o;
    o.x = *(uint32_t*)&lo;
    o.y = *(uint32_t*)&hi;
    dst[i] = o;
}

// ---------------- GEMM1: H = silu(Xe*Wg) * (Xe*Wu)  [fp16 m16n8k16] ----------------
// CTA tile: M=128 x N=64 (both G and U). 8 warps (4m x 2n), warp tile 32x32 each.
__global__ __launch_bounds__(256, 2) void gemm1_kernel() {
    const int e    = blockIdx.z;
    const int cnt  = g_counts[e];
    const int row0 = blockIdx.x * 128;
    if (row0 >= cnt) return;
    const int seg = g_offs[e];
    const int f0  = blockIdx.y * 64;

    extern __shared__ __half sm[];
    int* rid = (int*)(sm + G1_STGH * NSTG);

    const int tid = threadIdx.x, lane = tid & 31, warp = tid >> 5;
    const int grp = lane >> 2, t4 = lane & 3;

    if (tid < 128) {
        int r = row0 + tid;
        rid[tid] = (r < cnt) ? (g_rowmap[seg + r] >> 1) : -1;
    }
    __syncthreads();

    // loaders
    const int arow = tid >> 1, ach = (tid & 1);        // A: 2 x 16B
    const int tok  = rid[arow];
    const uint32_t aval = (tok >= 0) ? 16u : 0u;
    const __half* aptr = g_Xh + (size_t)(tok < 0 ? 0 : tok) * TD + ach * 16;
    const int krow = tid >> 3, nc = tid & 7;           // G/U: 1 x 16B each
    const __half* gptr = g_Wgh + ((size_t)e * TD + krow) * TF + f0 + nc * 8;
    const __half* uptr = g_Wuh + ((size_t)e * TD + krow) * TF + f0 + nc * 8;

    const uint32_t smb = smem_u32(sm);
    const uint32_t aoff = smb + arow * 80 + ach * 32;
    const uint32_t goff = smb + G1_GB * 2 + krow * 144 + nc * 16;
    const uint32_t uoff = smb + G1_UB * 2 + krow * 144 + nc * 16;
    const uint32_t SSB = G1_STGH * 2;

    #pragma unroll
    for (int s = 0; s < NSTG - 1; s++) {
        int kb = s * KC;
        cpa16(aoff + s * SSB,      aptr + kb,     aval);
        cpa16(aoff + s * SSB + 16, aptr + kb + 8, aval);
        cpa16(goff + s * SSB, gptr + (size_t)kb * TF, 16u);
        cpa16(uoff + s * SSB, uptr + (size_t)kb * TF, 16u);
        cpa_commit();
    }

    float accG[2][4][4], accU[2][4][4];
    #pragma unroll
    for (int i = 0; i < 2; i++)
        #pragma unroll
        for (int j = 0; j < 4; j++)
            #pragma unroll
            for (int q = 0; q < 4; q++) { accG[i][j][q] = 0.f; accU[i][j][q] = 0.f; }

    // ldmatrix lane maps
    const int mrow0 = (warp & 3) * 32;
    const int ncol0 = (warp >> 2) * 32;
    const int aR = mrow0 + ((lane >> 3) & 1) * 8 + (lane & 7);   // + mi*16
    const int aC = (lane >> 4) * 8;                              // + ks*16
    const int bR = ((lane >> 3) & 1) * 8 + (lane & 7);           // + ks*16 (k dir)
    const int bC = ncol0 + (lane >> 4) * 8;                      // + pair*16

    const int NC = TD / KC;   // 64
    #pragma unroll 1
    for (int i = 0; i < NC; i++) {
        cpa_wait2();
        __syncthreads();
        {
            int s = (i + NSTG - 1) & 3;
            int kb = (i + NSTG - 1) * KC;
            if (kb < TD) {
                cpa16(aoff + s * SSB,      aptr + kb,     aval);
                cpa16(aoff + s * SSB + 16, aptr + kb + 8, aval);
                cpa16(goff + s * SSB, gptr + (size_t)kb * TF, 16u);
                cpa16(uoff + s * SSB, uptr + (size_t)kb * TF, 16u);
            }
            cpa_commit();
        }
        const uint32_t sbase = smb + (i & 3) * SSB;
        #pragma unroll
        for (int ks = 0; ks < 2; ks++) {
            uint32_t a[2][4];
            #pragma unroll
            for (int mi = 0; mi < 2; mi++)
                ldmx4(a[mi], sbase + (aR + mi * 16) * 80 + (aC + ks * 16) * 2);
            uint32_t bg[2][4], bu[2][4];
            #pragma unroll
            for (int p = 0; p < 2; p++) {
                uint32_t ro = (bR + ks * 16) * 144 + (bC + p * 16) * 2;
                ldmx4t(bg[p], sbase + G1_GB * 2 + ro);
                ldmx4t(bu[p], sbase + G1_UB * 2 + ro);
            }
            #pragma unroll
            for (int p = 0; p < 2; p++)
                #pragma unroll
                for (int sub = 0; sub < 2; sub++) {
                    const int ni = p * 2 + sub;
                    #pragma unroll
                    for (int mi = 0; mi < 2; mi++) {
                        mma_f16(accG[mi][ni], a[mi], bg[p][sub * 2], bg[p][sub * 2 + 1]);
                        mma_f16(accU[mi][ni], a[mi], bu[p][sub * 2], bu[p][sub * 2 + 1]);
                    }
                }
        }
    }

    // epilogue: h = silu(g)*u -> g_Hh (fp16)
    #pragma unroll
    for (int mi = 0; mi < 2; mi++) {
        const int rl = (warp & 3) * 32 + mi * 16 + grp;
        const int r0 = row0 + rl, r1 = row0 + rl + 8;
        #pragma unroll
        for (int ni = 0; ni < 4; ni++) {
            const int col = f0 + (warp >> 2) * 32 + ni * 8 + t4 * 2;
            if (r0 < cnt) {
                float gg0 = accG[mi][ni][0], uu0 = accU[mi][ni][0];
                float gg1 = accG[mi][ni][1], uu1 = accU[mi][ni][1];
                float h0 = __fdividef(gg0 * uu0, 1.0f + __expf(-gg0));
                float h1 = __fdividef(gg1 * uu1, 1.0f + __expf(-gg1));
                *(__half2*)&g_Hh[(size_t)(seg + r0) * TF + col] = __floats2half2_rn(h0, h1);
            }
            if (r1 < cnt) {
                float gg0 = accG[mi][ni][2], uu0 = accU[mi][ni][2];
                float gg1 = accG[mi][ni][3], uu1 = accU[mi][ni][3];
                float h0 = __fdividef(gg0 * uu0, 1.0f + __expf(-gg0));
                float h1 = __fdividef(gg1 * uu1, 1.0f + __expf(-gg1));
                *(__half2*)&g_Hh[(size_t)(seg + r1) * TF + col] = __floats2half2_rn(h0, h1);
            }
        }
    }
}

// ---------------- GEMM2: Y = gate * (H * Wd)  [fp16 m16n8k16] ----------------
// CTA tile: M=128 x N=128. 8 warps (4m x 2n), warp tile 32x64.
__global__ __launch_bounds__(256, 2) void gemm2_kernel() {
    const int e    = blockIdx.z;
    const int cnt  = g_counts[e];
    const int row0 = blockIdx.x * 128;
    if (row0 >= cnt) return;
    const int seg = g_offs[e];
    const int n0  = blockIdx.y * 128;

    extern __shared__ __half sm[];
    const int tid = threadIdx.x, lane = tid & 31, warp = tid >> 5;
    const int grp = lane >> 2, t4 = lane & 3;

    const int arow = tid >> 1, ach = (tid & 1);
    const uint32_t aval = (row0 + arow < cnt) ? 16u : 0u;
    const __half* aptr = g_Hh + (size_t)(seg + ((row0 + arow < cnt) ? row0 + arow : 0)) * TF + ach * 16;
    const int krow = tid >> 3, nc = tid & 7;
    const __half* bptr = g_Wdh + ((size_t)e * TF + krow) * TD + n0 + nc * 8;

    const uint32_t smb = smem_u32(sm);
    const uint32_t aoff = smb + arow * 80 + ach * 32;
    const uint32_t b0off = smb + G2_B0 * 2 + krow * 144 + nc * 16;
    const uint32_t b1off = smb + G2_B1 * 2 + krow * 144 + nc * 16;
    const uint32_t SSB = G2_STGH * 2;

    #pragma unroll
    for (int s = 0; s < NSTG - 1; s++) {
        int kb = s * KC;
        cpa16(aoff + s * SSB,      aptr + kb,     aval);
        cpa16(aoff + s * SSB + 16, aptr + kb + 8, aval);
        cpa16(b0off + s * SSB, bptr + (size_t)kb * TD,      16u);
        cpa16(b1off + s * SSB, bptr + (size_t)kb * TD + 64, 16u);
        cpa_commit();
    }

    float acc[2][8][4];
    #pragma unroll
    for (int i = 0; i < 2; i++)
        #pragma unroll
        for (int j = 0; j < 8; j++)
            #pragma unroll
            for (int q = 0; q < 4; q++) acc[i][j][q] = 0.f;

    const int mrow0 = (warp & 3) * 32;
    const uint32_t sBbase = (warp >> 2) ? (G2_B1 * 2) : (G2_B0 * 2);  // warp n-half
    const int aR = mrow0 + ((lane >> 3) & 1) * 8 + (lane & 7);
    const int aC = (lane >> 4) * 8;
    const int bR = ((lane >> 3) & 1) * 8 + (lane & 7);
    const int bC = (lane >> 4) * 8;                                   // + pair*16 (within 64)

    const int NC = TF / KC;   // 256
    #pragma unroll 1
    for (int i = 0; i < NC; i++) {
        cpa_wait2();
        __syncthreads();
        {
            int s = (i + NSTG - 1) & 3;
            int kb = (i + NSTG - 1) * KC;
            if (kb < TF) {
                cpa16(aoff + s * SSB,      aptr + kb,     aval);
                cpa16(aoff + s * SSB + 16, aptr + kb + 8, aval);
                cpa16(b0off + s * SSB, bptr + (size_t)kb * TD,      16u);
                cpa16(b1off + s * SSB, bptr + (size_t)kb * TD + 64, 16u);
            }
            cpa_commit();
        }
        const uint32_t sbase = smb + (i & 3) * SSB;
        #pragma unroll
        for (int ks = 0; ks < 2; ks++) {
            uint32_t a[2][4];
            #pragma unroll
            for (int mi = 0; mi < 2; mi++)
                ldmx4(a[mi], sbase + (aR + mi * 16) * 80 + (aC + ks * 16) * 2);
            #pragma unroll
            for (int p = 0; p < 4; p++) {
                uint32_t bb[4];
                ldmx4t(bb, sbase + sBbase + (bR + ks * 16) * 144 + (bC + p * 16) * 2);
                #pragma unroll
                for (int sub = 0; sub < 2; sub++) {
                    const int ni = p * 2 + sub;
                    #pragma unroll
                    for (int mi = 0; mi < 2; mi++)
                        mma_f16(acc[mi][ni], a[mi], bb[sub * 2], bb[sub * 2 + 1]);
                }
            }
        }
    }

    // epilogue: scale by gate, scatter to assignment slot (fp32)
    #pragma unroll
    for (int mi = 0; mi < 2; mi++) {
        const int rl = (warp & 3) * 32 + mi * 16 + grp;
        const int r0 = row0 + rl, r1 = row0 + rl + 8;
        int a0i = 0, a1i = 0; float w0 = 0.f, w1 = 0.f;
        if (r0 < cnt) { a0i = g_rowmap[seg + r0]; w0 = g_rowgate[seg + r0]; }
        if (r1 < cnt) { a1i = g_rowmap[seg + r1]; w1 = g_rowgate[seg + r1]; }
        #pragma unroll
        for (int ni = 0; ni < 8; ni++) {
            const int col = n0 + (warp >> 2) * 64 + ni * 8 + t4 * 2;
            if (r0 < cnt) {
                float2 v; v.x = w0 * acc[mi][ni][0]; v.y = w0 * acc[mi][ni][1];
                *(float2*)&g_Y[(size_t)a0i * TD + col] = v;
            }
            if (r1 < cnt) {
                float2 v; v.x = w1 * acc[mi][ni][2]; v.y = w1 * acc[mi][ni][3];
                *(float2*)&g_Y[(size_t)a1i * TD + col] = v;
            }
        }
    }
}

// ---------------- combine ----------------
__global__ void combine_kernel(float* __restrict__ out) {
    int i = blockIdx.x * blockDim.x + threadIdx.x;
    if (i >= TT * TD) return;
    int t = i >> 11;
    int d = i & (TD - 1);
    out[i] = g_Y[(size_t)(2 * t) * TD + d] + g_Y[(size_t)(2 * t + 1) * TD + d];
}

// ---------------- launch ----------------
extern "C" void kernel_launch(void* const* d_in, const int* in_sizes, int n_in,
                              void* d_out, int out_size) {
    const float* x  = (const float*)d_in[0];
    const float* Wr = (const float*)d_in[1];
    const float* Wg = (const float*)d_in[2];
    const float* Wu = (const float*)d_in[3];
    const float* Wd = (const float*)d_in[4];
    float* out = (float*)d_out;

    static int attr_done = 0;
    if (!attr_done) {
        cudaFuncSetAttribute(gemm1_kernel, cudaFuncAttributeMaxDynamicSharedMemorySize, G1_SMEM);
        cudaFuncSetAttribute(gemm2_kernel, cudaFuncAttributeMaxDynamicSharedMemorySize, G2_SMEM);
        attr_done = 1;
    }

    zero_kernel<<<1, 32>>>();
    router_kernel<<<TT / 8, 256>>>(x, Wr);
    offsets_kernel<<<1, 1>>>();
    scatter_kernel<<<NA / 256, 256>>>();

    // fp32 -> fp16 prep
    {
        __half* xh; cudaGetSymbolAddress((void**)&xh, g_Xh);
        __half* wgh; cudaGetSymbolAddress((void**)&wgh, g_Wgh);
        __half* wuh; cudaGetSymbolAddress((void**)&wuh, g_Wuh);
        __half* wdh; cudaGetSymbolAddress((void**)&wdh, g_Wdh);
        int nx = TT * TD / 4;
        int nw = TE * TD * TF / 4;
        cvt_kernel<<<(nx + 255) / 256, 256>>>((const float4*)x,  (uint2*)xh,  nx);
        cvt_kernel<<<(nw + 255) / 256, 256>>>((const float4*)Wg, (uint2*)wgh, nw);
        cvt_kernel<<<(nw + 255) / 256, 256>>>((const float4*)Wu, (uint2*)wuh, nw);
        cvt_kernel<<<(nw + 255) / 256, 256>>>((const float4*)Wd, (uint2*)wdh, nw);
    }

    gemm1_kernel<<<dim3(16, TF / 64, TE), 256, G1_SMEM>>>();
    gemm2_kernel<<<dim3(16, TD / 128, TE), 256, G2_SMEM>>>();

    combine_kernel<<<(TT * TD) / 256, 256>>>(out);
}